// round 8
// baseline (speedup 1.0000x reference)
#include <cuda_runtime.h>
#include <cstdint>

// ---------------- config ----------------
#define CTAS        4096
#define THREADS     256              // 8 warps = 4 pairs; pair handles 64 rows
#define UNIT_ROWS   16
#define UNIT_BYTES  4096
#define NSLOTS      3
#define NUNITS      4                // 4 pairs * 64 rows * 4096 CTAs = 2^20
#define ROWS_CTA    256

// smem: FB (plain tf32 W [n][k], 16 KB; reused as partial buffer) + per-warp rings
#define FB_BYTES    16384
#define SMEM_X      FB_BYTES
#define SMEM_TOTAL  (FB_BYTES + 8 * NSLOTS * UNIT_BYTES)   // 114688 (R3-proven, 2 CTA/SM)

// ---------------- math constants ----------------
#define C_SCALE_L2E  4.3280851227f   // 3 * log2(e)
#define C_CLAMP_L2E 14.4269504089f   // 10 * log2(e)
#define C_LN2        0.6931471806f

// ---------------- helpers ----------------
static __device__ __forceinline__ uint32_t smem_u32(const void* p) {
    uint32_t a;
    asm("{ .reg .u64 t; cvta.to.shared.u64 t, %1; cvt.u32.u64 %0, t; }"
        : "=r"(a) : "l"(p));
    return a;
}
static __device__ __forceinline__ void cp16(uint32_t s, const void* g) {
    asm volatile("cp.async.cg.shared.global [%0], [%1], 16;" :: "r"(s), "l"(g));
}
#define CP_COMMIT() asm volatile("cp.async.commit_group;" ::: "memory")
#define CP_WAIT(n)  asm volatile("cp.async.wait_group %0;" :: "n"(n) : "memory")

static __device__ __forceinline__ float exp2_fast(float x) {
    float r; asm("ex2.approx.ftz.f32 %0, %1;" : "=f"(r) : "f"(x)); return r;
}
static __device__ __forceinline__ float lg2_fast(float x) {
    float r; asm("lg2.approx.f32 %0, %1;" : "=f"(r) : "f"(x)); return r;
}
static __device__ __forceinline__ float rcp_fast(float x) {
    float r; asm("rcp.approx.ftz.f32 %0, %1;" : "=f"(r) : "f"(x)); return r;
}
static __device__ __forceinline__ uint32_t f2tf32(float v) {
    uint32_t r; asm("cvt.rna.tf32.f32 %0, %1;" : "=r"(r) : "f"(v)); return r;
}
static __device__ __forceinline__ uint32_t lds32(const char* smem, uint32_t off) {
    return *reinterpret_cast<const uint32_t*>(smem + off);
}

// mma.sync m16n8k8 tf32
static __device__ __forceinline__ void mma_tf32(
    float* d, uint32_t a0, uint32_t a1, uint32_t a2, uint32_t a3,
    uint32_t b0, uint32_t b1) {
    asm volatile(
        "mma.sync.aligned.m16n8k8.row.col.f32.tf32.tf32.f32 "
        "{%0,%1,%2,%3}, {%4,%5,%6,%7}, {%8,%9}, {%0,%1,%2,%3};"
        : "+f"(d[0]), "+f"(d[1]), "+f"(d[2]), "+f"(d[3])
        : "r"(a0), "r"(a1), "r"(a2), "r"(a3), "r"(b0), "r"(b1));
}

static __device__ __forceinline__ float expv(float z) {
    float w = fminf(fmaxf(z * C_SCALE_L2E, -C_CLAMP_L2E), C_CLAMP_L2E);
    return exp2_fast(w);
}
// mish(ln s): e^(ln s) == s exactly -> tanh(softplus) = ((1+s)^2-1)/((1+s)^2+1)
static __device__ __forceinline__ float mish_of_ln(float s) {
    float lse = C_LN2 * lg2_fast(s);
    float up  = s + 1.0f;
    float q   = up * up;
    return lse * (q - 1.0f) * rcp_fast(q + 1.0f);
}

// load one 16-row unit (4 KB contiguous in gmem), XOR-swizzled dst (R3-identical)
static __device__ __forceinline__ void load_unit(
    uint32_t dst_base, const float* __restrict__ src, int lane) {
#pragma unroll
    for (int i = 0; i < 8; i++) {
        int idx = i * 32 + lane;            // 256 16B-chunks
        int r = idx >> 4, c = idx & 15;
        cp16(dst_base + (uint32_t)(r * 256 + ((c ^ (r & 7)) << 4)),
             src + (size_t)idx * 4);
    }
}

// ---------------- kernel ----------------
__global__ void __launch_bounds__(THREADS, 2) fused_lin_lse_mish(
    const float* __restrict__ x, const float* __restrict__ W,
    float* __restrict__ out) {
    extern __shared__ char smem[];
    const uint32_t sb = smem_u32(smem);
    const int tid  = threadIdx.x;
    const int lane = tid & 31;
    const int w    = tid >> 5;
    const int h    = w & 1;              // column half: cols 32h .. 32h+31
    const int pair = w >> 1;             // 0..3 -> rows pair*64 .. pair*64+63
    const int g    = lane >> 2;          // 0..7
    const int t    = lane & 3;           // 0..3

    const size_t crow0 = (size_t)blockIdx.x * ROWS_CTA;
    const size_t prow0 = crow0 + (size_t)pair * (NUNITS * UNIT_ROWS);
    const uint32_t ring = sb + SMEM_X + (uint32_t)w * (NSLOTS * UNIT_BYTES);

    // ---- prologue: each warp loads ITS OWN copy of units 0..2 (DRAM early) ----
#pragma unroll
    for (int s = 0; s < NSLOTS; s++) {
        load_unit(ring + (uint32_t)s * UNIT_BYTES,
                  x + (prow0 + (size_t)s * UNIT_ROWS) * 64, lane);
        CP_COMMIT();
    }

    // ---- FB: W as plain tf32 [n][k] ----
    uint32_t* FB = reinterpret_cast<uint32_t*>(smem);
#pragma unroll
    for (int i = 0; i < 16; i++)
        FB[i * THREADS + tid] = f2tf32(W[i * THREADS + tid]);
    __syncthreads();

    // ---- permanent B fragments for this warp's half (nb-blocks 4h..4h+3) ----
    uint32_t b[8][4][2];                 // [kb][nb][b0,b1]
#pragma unroll
    for (int kb = 0; kb < 8; kb++)
#pragma unroll
        for (int nb = 0; nb < 4; nb++) {
            int n = 32 * h + 8 * nb + g;
            b[kb][nb][0] = FB[n * 64 + 8 * kb + t];
            b[kb][nb][1] = FB[n * 64 + 8 * kb + 4 + t];
        }
    __syncthreads();                     // FB region now free -> partial buffer

    float* ps = reinterpret_cast<float*>(smem);   // ps[h*256 + local_row]

#pragma unroll
    for (int u = 0; u < NUNITS; u++) {
        CP_WAIT(2);                      // unit u resident (this warp's own loads)

        const char* As = smem + SMEM_X + (size_t)w * (NSLOTS * UNIT_BYTES)
                       + (size_t)(u % NSLOTS) * UNIT_BYTES;

        float acc[4][4];
#pragma unroll
        for (int nb = 0; nb < 4; nb++)
#pragma unroll
            for (int q = 0; q < 4; q++) acc[nb][q] = 0.0f;

#pragma unroll
        for (int kb = 0; kb < 8; kb++) {
            const uint32_t cx0 = (uint32_t)((((2 * kb) ^ g) << 4)) + (uint32_t)(t * 4);
            const uint32_t cx1 = (uint32_t)((((2 * kb + 1) ^ g) << 4)) + (uint32_t)(t * 4);
            uint32_t a0 = lds32(As, (uint32_t)(g * 256) + cx0);
            uint32_t a1 = lds32(As, (uint32_t)((g + 8) * 256) + cx0);
            uint32_t a2 = lds32(As, (uint32_t)(g * 256) + cx1);
            uint32_t a3 = lds32(As, (uint32_t)((g + 8) * 256) + cx1);
#pragma unroll
            for (int nb = 0; nb < 4; nb++)
                mma_tf32(acc[nb], a0, a1, a2, a3, b[kb][nb][0], b[kb][nb][1]);
        }

        // ---- partial sum of exp over this warp's 32 columns ----
        float sl = 0.0f, sh = 0.0f;
#pragma unroll
        for (int nb = 0; nb < 4; nb++) {
            sl += expv(acc[nb][0]) + expv(acc[nb][1]);
            sh += expv(acc[nb][2]) + expv(acc[nb][3]);
        }
        sl += __shfl_xor_sync(0xFFFFFFFF, sl, 1);
        sl += __shfl_xor_sync(0xFFFFFFFF, sl, 2);
        sh += __shfl_xor_sync(0xFFFFFFFF, sh, 1);
        sh += __shfl_xor_sync(0xFFFFFFFF, sh, 2);
        if (t == 0) {
            int loc = pair * 64 + u * 16 + g;
            ps[h * 256 + loc]     = sl;
            ps[h * 256 + loc + 8] = sh;
        }

        // ---- refill the slot just consumed (warp-private, R3-identical) ----
        if (u + NSLOTS < NUNITS)
            load_unit(ring + (uint32_t)(u % NSLOTS) * UNIT_BYTES,
                      x + (prow0 + (size_t)(u + NSLOTS) * UNIT_ROWS) * 64, lane);
        CP_COMMIT();                     // uniform group accounting (empty ok)
    }

    // ---- combine halves + mish (in-CTA; replaces second kernel) ----
    __syncthreads();
    float s = ps[tid] + ps[256 + tid];
    out[crow0 + tid] = mish_of_ln(s);
}

// ---------------- launch ----------------
extern "C" void kernel_launch(void* const* d_in, const int* in_sizes, int n_in,
                              void* d_out, int out_size) {
    (void)in_sizes; (void)n_in; (void)out_size;
    const float* x = (const float*)d_in[0];
    const float* W = (const float*)d_in[1];
    float* out = (float*)d_out;

    cudaFuncSetAttribute(fused_lin_lse_mish,
                         cudaFuncAttributeMaxDynamicSharedMemorySize, SMEM_TOTAL);
    fused_lin_lse_mish<<<CTAS, THREADS, SMEM_TOTAL>>>(x, W, out);
}

// round 9
// speedup vs baseline: 1.3067x; 1.3067x over previous
#include <cuda_runtime.h>
#include <cstdint>

// ---------------- config ----------------
#define CTAS        2048
#define THREADS     256              // 8 warps = 4 pairs; pair = 128 rows
#define UNIT_ROWS   16
#define NUNITS      8                // 8*16 = 128 rows per pair; 2048*512 = 2^20
#define ROWS_CTA    512
#define SMEM_TOTAL  16384            // W staging (reused as partial buffer 4 KB)

// ---------------- math constants ----------------
#define C_SCALE_L2E  4.3280851227f   // 3 * log2(e)
#define C_CLAMP_L2E 14.4269504089f   // 10 * log2(e)
#define C_LN2        0.6931471806f

// ---------------- helpers ----------------
static __device__ __forceinline__ float exp2_fast(float x) {
    float r; asm("ex2.approx.ftz.f32 %0, %1;" : "=f"(r) : "f"(x)); return r;
}
static __device__ __forceinline__ float lg2_fast(float x) {
    float r; asm("lg2.approx.f32 %0, %1;" : "=f"(r) : "f"(x)); return r;
}
static __device__ __forceinline__ float rcp_fast(float x) {
    float r; asm("rcp.approx.ftz.f32 %0, %1;" : "=f"(r) : "f"(x)); return r;
}
static __device__ __forceinline__ uint32_t f2tf32(float v) {
    uint32_t r; asm("cvt.rna.tf32.f32 %0, %1;" : "=r"(r) : "f"(v)); return r;
}

// mma.sync m16n8k8 tf32
static __device__ __forceinline__ void mma_tf32(
    float* d, uint32_t a0, uint32_t a1, uint32_t a2, uint32_t a3,
    uint32_t b0, uint32_t b1) {
    asm volatile(
        "mma.sync.aligned.m16n8k8.row.col.f32.tf32.tf32.f32 "
        "{%0,%1,%2,%3}, {%4,%5,%6,%7}, {%8,%9}, {%0,%1,%2,%3};"
        : "+f"(d[0]), "+f"(d[1]), "+f"(d[2]), "+f"(d[3])
        : "r"(a0), "r"(a1), "r"(a2), "r"(a3), "r"(b0), "r"(b1));
}

static __device__ __forceinline__ float expv(float z) {
    float w = fminf(fmaxf(z * C_SCALE_L2E, -C_CLAMP_L2E), C_CLAMP_L2E);
    return exp2_fast(w);
}
// mish(ln s): e^(ln s) == s exactly -> tanh(softplus) = ((1+s)^2-1)/((1+s)^2+1)
static __device__ __forceinline__ float mish_of_ln(float s) {
    float lse = C_LN2 * lg2_fast(s);
    float up  = s + 1.0f;
    float q   = up * up;
    return lse * (q - 1.0f) * rcp_fast(q + 1.0f);
}

// ---------------- kernel ----------------
__global__ void __launch_bounds__(THREADS, 2) fused_lin_lse_mish(
    const float* __restrict__ x, const float* __restrict__ W,
    float* __restrict__ out) {
    extern __shared__ float smf[];
    const int tid  = threadIdx.x;
    const int lane = tid & 31;
    const int w    = tid >> 5;
    const int h    = w & 1;              // column half: cols 32h .. 32h+31
    const int pair = w >> 1;             // 0..3 -> rows pair*128 .. pair*128+127
    const int g    = lane >> 2;          // 0..7
    const int t    = lane & 3;           // 0..3

    const size_t crow0 = (size_t)blockIdx.x * ROWS_CTA;

    // ---- stage W once (tf32) ----
    uint32_t* FB = reinterpret_cast<uint32_t*>(smf);
#pragma unroll
    for (int i = 0; i < 16; i++)
        FB[i * THREADS + tid] = f2tf32(W[i * THREADS + tid]);
    __syncthreads();

    // ---- permanent B fragments, permuted-K mapping ----
    // mma kb = 2*seg+m: k-slot t -> col 16seg+4t+2m, slot t+4 -> col+1
    uint32_t b[8][4][2];                 // [kb][nb][b0,b1]
#pragma unroll
    for (int kb = 0; kb < 8; kb++)
#pragma unroll
        for (int nb = 0; nb < 4; nb++) {
            int n   = 32 * h + 8 * nb + g;
            int col = 16 * (kb >> 1) + 4 * t + 2 * (kb & 1);
            b[kb][nb][0] = FB[n * 64 + col];
            b[kb][nb][1] = FB[n * 64 + col + 1];
        }
    __syncthreads();                     // FB region free -> partial buffer
    float* ps = smf;                     // ps[h*512 + local_row], 1024 floats

    // per-lane gmem base: row (pair*128 + g), float4-chunk t (cols 4t..4t+3)
    const float4* qlo = reinterpret_cast<const float4*>(
        x + (crow0 + (size_t)pair * 128 + g) * 64) + t;
    const float4* qhi = qlo + 8 * 16;    // +8 rows (16 float4 per row)

#pragma unroll
    for (int u = 0; u < NUNITS; u++) {
        // ---- direct-LDG A tile: 8x LDG.128 per lane pair-rows, 4 segs ----
        float4 flo[4], fhi[4];
#pragma unroll
        for (int seg = 0; seg < 4; seg++) {
            flo[seg] = qlo[(size_t)u * 256 + seg * 4];   // unit stride 16 rows = 256 float4
            fhi[seg] = qhi[(size_t)u * 256 + seg * 4];
        }

        float acc[4][4];
#pragma unroll
        for (int nb = 0; nb < 4; nb++)
#pragma unroll
            for (int q = 0; q < 4; q++) acc[nb][q] = 0.0f;

#pragma unroll
        for (int seg = 0; seg < 4; seg++) {
            uint32_t lx = f2tf32(flo[seg].x), ly = f2tf32(flo[seg].y);
            uint32_t lz = f2tf32(flo[seg].z), lw = f2tf32(flo[seg].w);
            uint32_t hx = f2tf32(fhi[seg].x), hy = f2tf32(fhi[seg].y);
            uint32_t hz = f2tf32(fhi[seg].z), hw = f2tf32(fhi[seg].w);
            // kb = 2*seg   : cols (+0,+1) -> (x, y)
#pragma unroll
            for (int nb = 0; nb < 4; nb++)
                mma_tf32(acc[nb], lx, hx, ly, hy,
                         b[2 * seg][nb][0], b[2 * seg][nb][1]);
            // kb = 2*seg+1 : cols (+2,+3) -> (z, w)
#pragma unroll
            for (int nb = 0; nb < 4; nb++)
                mma_tf32(acc[nb], lz, hz, lw, hw,
                         b[2 * seg + 1][nb][0], b[2 * seg + 1][nb][1]);
        }

        // ---- partial sum of exp over this warp's 32 columns ----
        float sl = 0.0f, sh = 0.0f;
#pragma unroll
        for (int nb = 0; nb < 4; nb++) {
            sl += expv(acc[nb][0]) + expv(acc[nb][1]);
            sh += expv(acc[nb][2]) + expv(acc[nb][3]);
        }
        sl += __shfl_xor_sync(0xFFFFFFFF, sl, 1);
        sl += __shfl_xor_sync(0xFFFFFFFF, sl, 2);
        sh += __shfl_xor_sync(0xFFFFFFFF, sh, 1);
        sh += __shfl_xor_sync(0xFFFFFFFF, sh, 2);
        if (t == 0) {
            int loc = pair * 128 + u * UNIT_ROWS + g;
            ps[h * 512 + loc]     = sl;
            ps[h * 512 + loc + 8] = sh;
        }
    }

    // ---- combine halves + mish ----
    __syncthreads();
#pragma unroll
    for (int rep = 0; rep < 2; rep++) {
        int r = rep * THREADS + tid;
        float s = ps[r] + ps[512 + r];
        out[crow0 + r] = mish_of_ln(s);
    }
}

// ---------------- launch ----------------
extern "C" void kernel_launch(void* const* d_in, const int* in_sizes, int n_in,
                              void* d_out, int out_size) {
    (void)in_sizes; (void)n_in; (void)out_size;
    const float* x = (const float*)d_in[0];
    const float* W = (const float*)d_in[1];
    float* out = (float*)d_out;

    cudaFuncSetAttribute(fused_lin_lse_mish,
                         cudaFuncAttributeMaxDynamicSharedMemorySize, SMEM_TOTAL);
    fused_lin_lse_mish<<<CTAS, THREADS, SMEM_TOTAL>>>(x, W, out);
}

// round 10
// speedup vs baseline: 1.4493x; 1.1091x over previous
#include <cuda_runtime.h>
#include <cstdint>

// ---------------- config ----------------
#define CTAS        2048
#define THREADS     256              // 8 warps = 4 pairs; pair owns 128 rows
#define UNIT_ROWS   16
#define UNIT_BYTES  4096
#define NSLOTS      4
#define NUNITS      8                // 4 pairs * 128 rows * 2048 CTAs = 2^20
#define ROWS_CTA    512

// smem layout (bytes)
#define FB_BYTES    16384            // tf32 W [n][k]
#define SMEM_RING   FB_BYTES
#define RING_PAIR   (NSLOTS * UNIT_BYTES)            // 16384 per pair
#define SMEM_PS     (SMEM_RING + 4 * RING_PAIR)      // 81920
#define PS_BYTES    4096                             // ps[2][512] floats
#define SMEM_BAR    (SMEM_PS + PS_BYTES)             // 86016
#define SMEM_TOTAL  (SMEM_BAR + 256)                 // 86272 -> 2 CTA/SM

// ---------------- math constants ----------------
#define C_SCALE_L2E  4.3280851227f   // 3 * log2(e)
#define C_CLAMP_L2E 14.4269504089f   // 10 * log2(e)
#define C_LN2        0.6931471806f

// ---------------- helpers ----------------
static __device__ __forceinline__ uint32_t smem_u32(const void* p) {
    uint32_t a;
    asm("{ .reg .u64 t; cvta.to.shared.u64 t, %1; cvt.u32.u64 %0, t; }"
        : "=r"(a) : "l"(p));
    return a;
}
static __device__ __forceinline__ void cp16(uint32_t s, const void* g) {
    asm volatile("cp.async.cg.shared.global [%0], [%1], 16;" :: "r"(s), "l"(g));
}
// async arrive on mbarrier when THIS thread's prior cp.asyncs complete
static __device__ __forceinline__ void cp_arrive(uint32_t bar) {
    asm volatile("cp.async.mbarrier.arrive.noinc.shared.b64 [%0];"
                 :: "r"(bar) : "memory");
}
#define MBAR_INIT(a, n) \
    asm volatile("mbarrier.init.shared.b64 [%0], %1;" :: "r"(a), "r"((uint32_t)(n)) : "memory")
#define MBAR_ARRIVE(a) \
    asm volatile("mbarrier.arrive.shared.b64 _, [%0];" :: "r"(a) : "memory")

static __device__ __forceinline__ void mbar_wait(uint32_t mbar, uint32_t parity) {
    uint32_t done;
    asm volatile("{ .reg .pred p;\n\t"
                 "mbarrier.try_wait.parity.shared.b64 p, [%1], %2;\n\t"
                 "selp.b32 %0, 1, 0, p; }"
                 : "=r"(done) : "r"(mbar), "r"(parity) : "memory");
    if (!done) {
        asm volatile("{ .reg .pred P1;\n\t"
                     "WL_%=:\n\t"
                     "mbarrier.try_wait.parity.shared.b64 P1, [%0], %1;\n\t"
                     "@P1 bra.uni WD_%=;\n\t"
                     "bra.uni WL_%=;\n\t"
                     "WD_%=: }"
                     :: "r"(mbar), "r"(parity) : "memory");
    }
}

static __device__ __forceinline__ float exp2_fast(float x) {
    float r; asm("ex2.approx.ftz.f32 %0, %1;" : "=f"(r) : "f"(x)); return r;
}
static __device__ __forceinline__ float lg2_fast(float x) {
    float r; asm("lg2.approx.f32 %0, %1;" : "=f"(r) : "f"(x)); return r;
}
static __device__ __forceinline__ float rcp_fast(float x) {
    float r; asm("rcp.approx.ftz.f32 %0, %1;" : "=f"(r) : "f"(x)); return r;
}
static __device__ __forceinline__ uint32_t f2tf32(float v) {
    uint32_t r; asm("cvt.rna.tf32.f32 %0, %1;" : "=r"(r) : "f"(v)); return r;
}
static __device__ __forceinline__ uint32_t lds32(const char* smem, uint32_t off) {
    return *reinterpret_cast<const uint32_t*>(smem + off);
}

// mma.sync m16n8k8 tf32
static __device__ __forceinline__ void mma_tf32(
    float* d, uint32_t a0, uint32_t a1, uint32_t a2, uint32_t a3,
    uint32_t b0, uint32_t b1) {
    asm volatile(
        "mma.sync.aligned.m16n8k8.row.col.f32.tf32.tf32.f32 "
        "{%0,%1,%2,%3}, {%4,%5,%6,%7}, {%8,%9}, {%0,%1,%2,%3};"
        : "+f"(d[0]), "+f"(d[1]), "+f"(d[2]), "+f"(d[3])
        : "r"(a0), "r"(a1), "r"(a2), "r"(a3), "r"(b0), "r"(b1));
}

static __device__ __forceinline__ float expv(float z) {
    float w = fminf(fmaxf(z * C_SCALE_L2E, -C_CLAMP_L2E), C_CLAMP_L2E);
    return exp2_fast(w);
}
// mish(ln s): e^(ln s) == s exactly -> tanh(softplus) = ((1+s)^2-1)/((1+s)^2+1)
static __device__ __forceinline__ float mish_of_ln(float s) {
    float lse = C_LN2 * lg2_fast(s);
    float up  = s + 1.0f;
    float q   = up * up;
    return lse * (q - 1.0f) * rcp_fast(q + 1.0f);
}

// load one 16-row unit (4 KB contiguous in gmem), XOR-swizzled dst (R3-proven)
static __device__ __forceinline__ void load_unit(
    uint32_t dst_base, const float* __restrict__ src, int lane) {
#pragma unroll
    for (int i = 0; i < 8; i++) {
        int idx = i * 32 + lane;            // 256 16B-chunks
        int r = idx >> 4, c = idx & 15;
        cp16(dst_base + (uint32_t)(r * 256 + ((c ^ (r & 7)) << 4)),
             src + (size_t)idx * 4);
    }
}

// ---------------- kernel ----------------
__global__ void __launch_bounds__(THREADS, 2) fused_lin_lse_mish(
    const float* __restrict__ x, const float* __restrict__ W,
    float* __restrict__ out) {
    extern __shared__ char smem[];
    const uint32_t sb = smem_u32(smem);
    const int tid  = threadIdx.x;
    const int lane = tid & 31;
    const int w    = tid >> 5;
    const int h    = w & 1;              // column half: cols 32h .. 32h+31
    const int pair = w >> 1;             // 0..3 -> rows pair*128 .. +127
    const int g    = lane >> 2;          // 0..7
    const int t    = lane & 3;           // 0..3

    const size_t crow0 = (size_t)blockIdx.x * ROWS_CTA;
    const size_t prow0 = crow0 + (size_t)pair * (NUNITS * UNIT_ROWS);
    const uint32_t ring = sb + SMEM_RING + (uint32_t)pair * RING_PAIR;
    const uint32_t barF = sb + SMEM_BAR + (uint32_t)pair * 64;        // full[s] = +8s
    const uint32_t barE = barF + 32;                                  // empty[s] = +8s

    // ---- init mbarriers (full: 32 async arrives; empty: 1 elected arrive) ----
    if (tid < 16) {
        int p = tid >> 2, s = tid & 3;
        MBAR_INIT(sb + SMEM_BAR + p * 64 + s * 8, 32);
        MBAR_INIT(sb + SMEM_BAR + p * 64 + 32 + s * 8, 1);
    }
    __syncthreads();

    // ---- prologue: warp h produces units h, h+2 into slots h, h+2 ----
#pragma unroll
    for (int s = 0; s < NSLOTS; s++) {
        if ((s & 1) == h) {
            load_unit(ring + (uint32_t)s * UNIT_BYTES,
                      x + (prow0 + (size_t)s * UNIT_ROWS) * 64, lane);
            cp_arrive(barF + (uint32_t)s * 8);
        }
    }

    // ---- stage W once (tf32) ----
    uint32_t* FB = reinterpret_cast<uint32_t*>(smem);
#pragma unroll
    for (int i = 0; i < 16; i++)
        FB[i * THREADS + tid] = f2tf32(W[i * THREADS + tid]);
    __syncthreads();

    // ---- permanent B fragments for half h (nb-blocks 4h..4h+3) ----
    uint32_t b[8][4][2];                 // [kb][nb][b0,b1]
#pragma unroll
    for (int kb = 0; kb < 8; kb++)
#pragma unroll
        for (int nb = 0; nb < 4; nb++) {
            int n = 32 * h + 8 * nb + g;
            b[kb][nb][0] = FB[n * 64 + 8 * kb + t];
            b[kb][nb][1] = FB[n * 64 + 8 * kb + 4 + t];
        }

    float* ps = reinterpret_cast<float*>(smem + SMEM_PS);  // ps[h*512 + row]

#pragma unroll
    for (int u = 0; u < NUNITS; u++) {
        const uint32_t s = (uint32_t)(u & 3);
        // data ready (producer's cp.asyncs completed -> 32 async arrives)
        mbar_wait(barF + s * 8, (uint32_t)((u >> 2) & 1));

        const char* As = smem + SMEM_RING + (size_t)pair * RING_PAIR
                       + (size_t)s * UNIT_BYTES;

        float acc[4][4];
#pragma unroll
        for (int nb = 0; nb < 4; nb++)
#pragma unroll
            for (int q = 0; q < 4; q++) acc[nb][q] = 0.0f;

#pragma unroll
        for (int kb = 0; kb < 8; kb++) {
            const uint32_t cx0 = (uint32_t)((((2 * kb) ^ g) << 4)) + (uint32_t)(t * 4);
            const uint32_t cx1 = (uint32_t)((((2 * kb + 1) ^ g) << 4)) + (uint32_t)(t * 4);
            uint32_t a0 = lds32(As, (uint32_t)(g * 256) + cx0);
            uint32_t a1 = lds32(As, (uint32_t)((g + 8) * 256) + cx0);
            uint32_t a2 = lds32(As, (uint32_t)(g * 256) + cx1);
            uint32_t a3 = lds32(As, (uint32_t)((g + 8) * 256) + cx1);
#pragma unroll
            for (int nb = 0; nb < 4; nb++)
                mma_tf32(acc[nb], a0, a1, a2, a3, b[kb][nb][0], b[kb][nb][1]);
        }

        // ---- partial sum of exp over this warp's 32 columns ----
        float sl = 0.0f, sh = 0.0f;
#pragma unroll
        for (int nb = 0; nb < 4; nb++) {
            sl += expv(acc[nb][0]) + expv(acc[nb][1]);
            sh += expv(acc[nb][2]) + expv(acc[nb][3]);
        }
        sl += __shfl_xor_sync(0xFFFFFFFF, sl, 1);
        sl += __shfl_xor_sync(0xFFFFFFFF, sl, 2);
        sh += __shfl_xor_sync(0xFFFFFFFF, sh, 1);
        sh += __shfl_xor_sync(0xFFFFFFFF, sh, 2);
        if (t == 0) {
            int loc = pair * 128 + u * UNIT_ROWS + g;
            ps[h * 512 + loc]     = sl;
            ps[h * 512 + loc + 8] = sh;
        }

        // ---- slot handoff ----
        if ((u & 1) == h) {
            // I produced u; refill slot s with unit u+4 once partner released it
            if (u + NSLOTS < NUNITS) {
                mbar_wait(barE + s * 8, (uint32_t)((u >> 2) & 1));
                load_unit(ring + s * UNIT_BYTES,
                          x + (prow0 + (size_t)(u + NSLOTS) * UNIT_ROWS) * 64, lane);
                cp_arrive(barF + s * 8);
            }
        } else {
            // partner produced u; release the slot (single elected arrive)
            if (lane == 0) MBAR_ARRIVE(barE + s * 8);
        }
    }

    // ---- combine halves + mish (one sync, end of kernel) ----
    __syncthreads();
#pragma unroll
    for (int rep = 0; rep < 2; rep++) {
        int r = rep * THREADS + tid;
        float sfull = ps[r] + ps[512 + r];
        out[crow0 + r] = mish_of_ln(sfull);
    }
}

// ---------------- launch ----------------
extern "C" void kernel_launch(void* const* d_in, const int* in_sizes, int n_in,
                              void* d_out, int out_size) {
    (void)in_sizes; (void)n_in; (void)out_size;
    const float* x = (const float*)d_in[0];
    const float* W = (const float*)d_in[1];
    float* out = (float*)d_out;

    cudaFuncSetAttribute(fused_lin_lse_mish,
                         cudaFuncAttributeMaxDynamicSharedMemorySize, SMEM_TOTAL);
    fused_lin_lse_mish<<<CTAS, THREADS, SMEM_TOTAL>>>(x, W, out);
}